// round 13
// baseline (speedup 1.0000x reference)
#include <cuda_runtime.h>

#define BS_  8192
#define NS_  30
#define KH_  14      // each side eliminates 14 blocks; interface blocks 14,15
#define E_   32      // elements per block
#define TPB  64      // lane 2k = top half of elem k, lane 2k+1 = bottom half

#define SV_V 5       // float4 vectors per record (20 floats, 80B stride)
#define SV_BYTES (SV_V * 16 * KH_ * TPB)   // 71680 B dynamic smem

// Streaming block elimination via adjugate inverse (1 RCP, parallel FMA trees).
// Record: invD (6), A original (9), g = invD*r0 (3).
#define ELIM_STEP(SVIDX) do {                                                    \
    float adj00 = D011*D022 - D021*D021;                                         \
    float adj10 = D020*D021 - D010*D022;                                         \
    float adj20 = D010*D021 - D011*D020;                                         \
    float adj11 = D000*D022 - D020*D020;                                         \
    float adj21 = D010*D020 - D000*D021;                                         \
    float adj22 = D000*D011 - D010*D010;                                         \
    float det = D000*adj00 + D010*adj10 + D020*adj20;                            \
    float idet; asm("rcp.approx.f32 %0, %1;" : "=f"(idet) : "f"(det));           \
    float i00=adj00*idet, i10=adj10*idet, i20=adj20*idet;                        \
    float i11=adj11*idet, i21=adj21*idet, i22=adj22*idet;                        \
    float g0 = i00*r00 + i10*r01 + i20*r02;                                      \
    float g1 = i10*r00 + i11*r01 + i21*r02;                                      \
    float g2 = i20*r00 + i21*r01 + i22*r02;                                      \
    float W00 = A00*i00 + A01*i10 + A02*i20;                                     \
    float W01 = A00*i10 + A01*i11 + A02*i21;                                     \
    float W02 = A00*i20 + A01*i21 + A02*i22;                                     \
    float W10 = A10*i00 + A11*i10 + A12*i20;                                     \
    float W11 = A10*i10 + A11*i11 + A12*i21;                                     \
    float W12 = A10*i20 + A11*i21 + A12*i22;                                     \
    float W20 = A20*i00 + A21*i10 + A22*i20;                                     \
    float W21 = A20*i10 + A21*i11 + A22*i21;                                     \
    float W22 = A20*i20 + A21*i21 + A22*i22;                                     \
    r10 -= A00*g0 + A01*g1 + A02*g2;                                             \
    r11 -= A10*g0 + A11*g1 + A12*g2;                                             \
    r12 -= A20*g0 + A21*g1 + A22*g2;                                             \
    r21 += g1;                                                                   \
    D100 -= W00*A00 + W01*A01 + W02*A02;                                         \
    D110 -= W10*A00 + W11*A01 + W12*A02;                                         \
    D120 -= W20*A00 + W21*A01 + W22*A02;                                         \
    D111 -= W10*A10 + W11*A11 + W12*A12;                                         \
    D121 -= W20*A10 + W21*A11 + W22*A12;                                         \
    D122 -= W20*A20 + W21*A21 + W22*A22;                                         \
    B10 += i10*A00 + i11*A01 + i21*A02;                                          \
    B11 += i10*A10 + i11*A11 + i21*A12;                                          \
    B12 += i10*A20 + i11*A21 + i21*A22;                                          \
    D211 -= i11;                                                                 \
    {                                                                            \
        float4* sp = ((float4*)s_sv) + ((SVIDX)*TPB + tid)*SV_V;                 \
        sp[0] = make_float4(i00, i10, i20, i11);                                 \
        sp[1] = make_float4(i21, i22, A00, A01);                                 \
        sp[2] = make_float4(A02, A10, A11, A12);                                 \
        sp[3] = make_float4(A20, A21, A22, g0);                                  \
        sp[4] = make_float4(g1, g2, 0.f, 0.f);                                   \
    }                                                                            \
    D000=D100; D010=D110; D020=D120; D011=D111; D021=D121; D022=D122;            \
    D100=0; D110=0; D120=0; D111=D211; D121=0; D122=0; D211=0;                   \
    A00=0; A01=0; A02=0; A10=B10; A11=B11; A12=B12; A20=0; A21=0; A22=0;         \
    B10=0; B11=0; B12=0;                                                         \
    r00=r10; r01=r11; r02=r12;                                                   \
    r10=0; r11=r21; r12=0; r21=0;                                                \
} while(0)

__global__ __launch_bounds__(TPB)
void ode_babe_kernel(const float* __restrict__ coeffs,
                     const float* __restrict__ rhs,
                     const float* __restrict__ ivr,
                     const float* __restrict__ steps,
                     float* __restrict__ out)
{
    __shared__ float s_co[E_ * 90];   // coeffs in; reused for x out
    __shared__ float s_rr[E_ * 30];
    __shared__ float s_st[E_ * 29];
    __shared__ float s_iv[E_ * 4];
    extern __shared__ float s_sv[];   // factor records (dynamic, float4-packed)

    const int tid = threadIdx.x;
    const size_t blk = (size_t)blockIdx.x * E_;

    // ---- coalesced staging ----
    {
        const float4* g = (const float4*)(coeffs + blk * 90);
        float4* s = (float4*)s_co;
        for (int k = tid; k < E_*90/4; k += TPB) s[k] = g[k];
    }
    {
        const float4* g = (const float4*)(rhs + blk * 30);
        float4* s = (float4*)s_rr;
        for (int k = tid; k < E_*30/4; k += TPB) s[k] = g[k];
    }
    {
        const float4* g = (const float4*)(steps + blk * 29);
        float4* s = (float4*)s_st;
        for (int k = tid; k < E_*29/4; k += TPB) s[k] = g[k];
    }
    {
        const float4* g = (const float4*)(ivr + blk * 4);
        float4* s = (float4*)s_iv;
        for (int k = tid; k < E_*4/4; k += TPB) s[k] = g[k];
    }
    __syncthreads();

    const int  e   = tid >> 1;          // element index within block
    const bool top = (tid & 1) == 0;    // even lane = top, odd = bottom

    const float* cc  = s_co + e * 90;
    const float* rrp = s_rr + e * 30;
    const float* stp = s_st + e * 29;

    // direction constants (uniform code path)
    const float sgn   = top ? 1.f : -1.f;
    const int   cbase = top ? 0 : 87;
    const int   cstep = top ? 3 : -3;
    const int   rbase = top ? 0 : 29;
    const int   rstep = top ? 1 : -1;
    const int   hbase = top ? 0 : 28;
    const int   hstep = top ? 1 : -1;

    const float one_t = top ? 1.f : 0.f;
    const float iva0 = top ? s_iv[e*4+0] : 0.f;
    const float iva1 = top ? s_iv[e*4+1] : 0.f;
    const float iva2 = top ? s_iv[e*4+2] : 0.f;
    const float iva3 = top ? s_iv[e*4+3] : 0.f;

    float D000=0,D010=0,D020=0,D011=0,D021=0,D022=0;
    float D100=0,D110=0,D120=0,D111=0,D121=0,D122=0;
    float D211=0;
    float A00=0,A01=0,A02=0,A10=0,A11=0,A12=0,A20=0,A21=0,A22=0;
    float B10=0,B11=0,B12=0;
    float r00=0,r01=0,r02=0, r10=0,r11=0,r12=0, r21=0;

    #pragma unroll
    for (int s = 0; s < KH_; s++) {
        const float* cb = cc + cbase + cstep*s;
        float c0=cb[0], c1=cb[1], c2=cb[2];
        float rv = rrp[rbase + rstep*s];

        D000 += c0*c0; D010 += c1*c0; D020 += c2*c0;
        D011 += c1*c1; D021 += c2*c1; D022 += c2*c2;
        r00 += c0*rv; r01 += c1*rv; r02 += c2*rv;
        if (s == 0) { D000 += one_t; D011 += one_t; r00 += iva0; r01 += iva1; }
        if (s == 1) { D000 += one_t; D011 += one_t; r00 += iva2; r01 += iva3; }

        float h = sgn * stp[hbase + hstep*s];
        float h2 = h*h, h3 = h2*h, h4 = h2*h2;
        D000 += 2.f;       D010 += h;          D020 += 0.5f*h2;
        D011 += 3.f*h2;    D021 += 1.5f*h3;    D022 += 1.25f*h4;
        A00  += -2.f;      A01  += -h;         A02  += -0.5f*h2;
        A10  += h;         A11  += -2.f*h2;    A12  += -h3;
        A20  += -0.5f*h2;  A21  += h3;
        D100 += 2.f;       D110 += -h;         D120 += 0.5f*h2;
        D111 += 3.f*h2;    D121 += -1.5f*h3;   D122 += 1.25f*h4;

        float cp = h + sgn * stp[hbase + hstep*(s+1)];
        D011 += 1.f;  A21 += cp;
        D122 += cp*cp; B12 += -cp; D211 += 1.f;

        ELIM_STEP(s);
    }

    // ---- interface carry exchange via warp shuffle (partner = lane^1) ----
    float te[14], be[14];
    {
        float mine[14] = { D000, D010, D020, D011, D021, D022, D111,
                           A10, A11, A12, r00, r01, r02, r11 };
        #pragma unroll
        for (int i = 0; i < 14; i++) {
            float theirs = __shfl_xor_sync(0xffffffffu, mine[i], 1);
            te[i] = top ? mine[i] : theirs;
            be[i] = top ? theirs  : mine[i];
        }
    }

    // ---- interface: 6x6 SPD solve for x_14, x_15 (computed by both lanes) ----
    float x10_, x11_, x12_, x20_, x21_, x22_;
    {
        float h = stp[KH_];
        float h2 = h*h, h3 = h2*h, h4 = h2*h2;
        float cK0=cc[3*KH_], cK1=cc[3*KH_+1], cK2=cc[3*KH_+2];
        float cL0=cc[3*KH_+3], cL1=cc[3*KH_+4], cL2=cc[3*KH_+5];
        float rvK = rrp[KH_], rvL = rrp[KH_+1];

        float d00 = te[0] + cK0*cK0 + 2.f;
        float d10 = te[1] + cK1*cK0 + h;
        float d20 = te[2] + cK2*cK0 + 0.5f*h2;
        float d11 = te[3] + cK1*cK1 + 3.f*h2 + be[6];
        float d21 = te[4] + cK2*cK1 + 1.5f*h3;
        float d22 = te[5] + cK2*cK2 + 1.25f*h4;
        float e00 = be[0] + cL0*cL0 + 2.f;
        float e10 = be[1] + cL1*cL0 - h;
        float e20 = be[2] + cL2*cL0 + 0.5f*h2;
        float e11 = be[3] + cL1*cL1 + 3.f*h2 + te[6];
        float e21 = be[4] + cL2*cL1 - 1.5f*h3;
        float e22 = be[5] + cL2*cL2 + 1.25f*h4;
        float a00 = -2.f;
        float a01 = -h        + be[7];
        float a02 = -0.5f*h2;
        float a10 =  h        + te[7];
        float a11 = -2.f*h2   + te[8] + be[8];
        float a12 = -h3       + te[9];
        float a20 = -0.5f*h2;
        float a21 =  h3       + be[9];
        float a22 = 0.f;
        float rk0 = te[10] + cK0*rvK;
        float rk1 = te[11] + cK1*rvK + be[13];
        float rk2 = te[12] + cK2*rvK;
        float rl0 = be[10] + cL0*rvL;
        float rl1 = be[11] + cL1*rvL + te[13];
        float rl2 = be[12] + cL2*rvL;

        float il00 = rsqrtf(d00);
        float l10 = d10*il00, l20 = d20*il00;
        float il11 = rsqrtf(d11 - l10*l10);
        float l21 = (d21 - l20*l10)*il11;
        float il22 = rsqrtf(d22 - l20*l20 - l21*l21);
        float w00 = a00*il00, w01 = (a01 - w00*l10)*il11, w02 = (a02 - w00*l20 - w01*l21)*il22;
        float w10 = a10*il00, w11 = (a11 - w10*l10)*il11, w12 = (a12 - w10*l20 - w11*l21)*il22;
        float w20 = a20*il00, w21 = (a21 - w20*l10)*il11, w22 = (a22 - w20*l20 - w21*l21)*il22;
        float s00 = e00 - (w00*w00 + w01*w01 + w02*w02);
        float s10 = e10 - (w10*w00 + w11*w01 + w12*w02);
        float s20 = e20 - (w20*w00 + w21*w01 + w22*w02);
        float s11 = e11 - (w10*w10 + w11*w11 + w12*w12);
        float s21 = e21 - (w20*w10 + w21*w11 + w22*w12);
        float s22 = e22 - (w20*w20 + w21*w21 + w22*w22);
        float jl00 = rsqrtf(s00);
        float k10 = s10*jl00, k20 = s20*jl00;
        float jl11 = rsqrtf(s11 - k10*k10);
        float k21 = (s21 - k20*k10)*jl11;
        float jl22 = rsqrtf(s22 - k20*k20 - k21*k21);
        float y10 = rk0*il00;
        float y11 = (rk1 - y10*l10)*il11;
        float y12 = (rk2 - y10*l20 - y11*l21)*il22;
        float t0 = rl0 - (w00*y10 + w01*y11 + w02*y12);
        float t1 = rl1 - (w10*y10 + w11*y11 + w12*y12);
        float t2 = rl2 - (w20*y10 + w21*y11 + w22*y12);
        float y20 = t0*jl00;
        float y21 = (t1 - y20*k10)*jl11;
        float y22 = (t2 - y20*k20 - y21*k21)*jl22;
        x22_ = y22*jl22;
        x21_ = (y21 - k21*x22_)*jl11;
        x20_ = (y20 - k10*x21_ - k20*x22_)*jl00;
        float z0 = y10 - (w00*x20_ + w10*x21_ + w20*x22_);
        float z1 = y11 - (w01*x20_ + w11*x21_ + w21*x22_);
        float z2 = y12 - (w02*x20_ + w12*x21_ + w22*x22_);
        x12_ = z2*il22;
        x11_ = (z1 - l21*x12_)*il11;
        x10_ = (z0 - l10*x11_ - l20*x12_)*il00;
    }

    // ---- back substitution: x = g - invD*(A^T x_next - xp1*e1) ----
    float* ox = s_co + e * 90;   // coeffs consumed; reuse as output staging
    if (top) {
        ox[3*KH_+0]=x10_; ox[3*KH_+1]=x11_; ox[3*KH_+2]=x12_;
        ox[3*KH_+3]=x20_; ox[3*KH_+4]=x21_; ox[3*KH_+5]=x22_;
    }
    float xn0 = top ? x10_ : x20_;
    float xn1 = top ? x11_ : x21_;
    float xn2 = top ? x12_ : x22_;
    float xp1 = top ? x21_ : x11_;
    const int obase = top ? 0 : 87;
    const int ostep = top ? 3 : -3;

    const float4* sb = (const float4*)s_sv;
    float4 p0, p1, p2, p3, p4;
    {
        const float4* sp = sb + ((KH_-1)*TPB + tid)*SV_V;
        p0 = sp[0]; p1 = sp[1]; p2 = sp[2]; p3 = sp[3]; p4 = sp[4];
    }

    #pragma unroll
    for (int k = KH_-1; k >= 0; k--) {
        float4 q0 = p0, q1 = p1, q2 = p2, q3 = p3, q4 = p4;
        if (k > 0) {   // prefetch next record off the chain
            const float4* sp = sb + ((k-1)*TPB + tid)*SV_V;
            p0 = sp[0]; p1 = sp[1]; p2 = sp[2]; p3 = sp[3]; p4 = sp[4];
        }
        // fields: q0=(i00,i10,i20,i11) q1=(i21,i22,A00,A01)
        //         q2=(A02,A10,A11,A12) q3=(A20,A21,A22,g0) q4=(g1,g2,-,-)
        float t0 = q1.z*xn0 + q2.y*xn1 + q3.x*xn2;          // A^T x: col0
        float t1 = q1.w*xn0 + q2.z*xn1 + q3.y*xn2 - xp1;    // col1 - xp1
        float t2 = q2.x*xn0 + q2.w*xn1 + q3.z*xn2;          // col2
        float x0 = q3.w - (q0.x*t0 + q0.y*t1 + q0.z*t2);
        float x1 = q4.x - (q0.y*t0 + q0.w*t1 + q1.x*t2);
        float x2 = q4.y - (q0.z*t0 + q1.x*t1 + q1.y*t2);
        float* op = ox + obase + ostep*k;
        op[0] = x0; op[1] = x1; op[2] = x2;
        xp1 = xn1; xn0 = x0; xn1 = x1; xn2 = x2;
    }

    // ---- coalesced store-out ----
    __syncthreads();
    {
        const float4* s = (const float4*)s_co;
        float4* g = (float4*)(out + blk * 90);
        for (int k = tid; k < E_*90/4; k += TPB) g[k] = s[k];
    }
}

extern "C" void kernel_launch(void* const* d_in, const int* in_sizes, int n_in,
                              void* d_out, int out_size) {
    const float* coeffs = (const float*)d_in[0];
    const float* rhs    = (const float*)d_in[1];
    const float* iv_rhs = (const float*)d_in[2];
    const float* steps  = (const float*)d_in[3];
    float* out = (float*)d_out;

    cudaFuncSetAttribute(ode_babe_kernel,
                         cudaFuncAttributeMaxDynamicSharedMemorySize, SV_BYTES);

    dim3 block(TPB);
    dim3 grid(BS_ / E_);   // 256 blocks
    ode_babe_kernel<<<grid, block, SV_BYTES>>>(coeffs, rhs, iv_rhs, steps, out);
}

// round 14
// speedup vs baseline: 1.0045x; 1.0045x over previous
#include <cuda_runtime.h>

#define BS_  8192
#define NS_  30
#define KH_  14      // each side eliminates 14 blocks; interface blocks 14,15
#define E_   32      // elements per block
#define TPB  64      // lane 2k = top half of elem k, lane 2k+1 = bottom half

#define SV_V 5       // record stride: 5 float4 (80B) keeps 8-lane LDS.128 conflict-free
#define SV_BYTES (SV_V * 16 * KH_ * TPB)   // 71680 B dynamic smem

// Streaming block elimination via adjugate inverse (1 RCP, parallel FMA trees).
// Record stored: W = A*invD (9), g = invD*r0 (3), invD col1 (3).  4 vecs used.
#define ELIM_STEP(SVIDX) do {                                                    \
    float adj00 = D011*D022 - D021*D021;                                         \
    float adj10 = D020*D021 - D010*D022;                                         \
    float adj20 = D010*D021 - D011*D020;                                         \
    float adj11 = D000*D022 - D020*D020;                                         \
    float adj21 = D010*D020 - D000*D021;                                         \
    float adj22 = D000*D011 - D010*D010;                                         \
    float det = D000*adj00 + D010*adj10 + D020*adj20;                            \
    float idet; asm("rcp.approx.f32 %0, %1;" : "=f"(idet) : "f"(det));           \
    float i00=adj00*idet, i10=adj10*idet, i20=adj20*idet;                        \
    float i11=adj11*idet, i21=adj21*idet, i22=adj22*idet;                        \
    float g0 = i00*r00 + i10*r01 + i20*r02;                                      \
    float g1 = i10*r00 + i11*r01 + i21*r02;                                      \
    float g2 = i20*r00 + i21*r01 + i22*r02;                                      \
    float W00 = A00*i00 + A01*i10 + A02*i20;                                     \
    float W01 = A00*i10 + A01*i11 + A02*i21;                                     \
    float W02 = A00*i20 + A01*i21 + A02*i22;                                     \
    float W10 = A10*i00 + A11*i10 + A12*i20;                                     \
    float W11 = A10*i10 + A11*i11 + A12*i21;                                     \
    float W12 = A10*i20 + A11*i21 + A12*i22;                                     \
    float W20 = A20*i00 + A21*i10 + A22*i20;                                     \
    float W21 = A20*i10 + A21*i11 + A22*i21;                                     \
    float W22 = A20*i20 + A21*i21 + A22*i22;                                     \
    r10 -= A00*g0 + A01*g1 + A02*g2;                                             \
    r11 -= A10*g0 + A11*g1 + A12*g2;                                             \
    r12 -= A20*g0 + A21*g1 + A22*g2;                                             \
    r21 += g1;                                                                   \
    D100 -= W00*A00 + W01*A01 + W02*A02;                                         \
    D110 -= W10*A00 + W11*A01 + W12*A02;                                         \
    D120 -= W20*A00 + W21*A01 + W22*A02;                                         \
    D111 -= W10*A10 + W11*A11 + W12*A12;                                         \
    D121 -= W20*A10 + W21*A11 + W22*A12;                                         \
    D122 -= W20*A20 + W21*A21 + W22*A22;                                         \
    B10 += i10*A00 + i11*A01 + i21*A02;                                          \
    B11 += i10*A10 + i11*A11 + i21*A12;                                          \
    B12 += i10*A20 + i11*A21 + i21*A22;                                          \
    D211 -= i11;                                                                 \
    {                                                                            \
        float4* sp = ((float4*)s_sv) + ((SVIDX)*TPB + tid)*SV_V;                 \
        sp[0] = make_float4(W00, W01, W02, g0);                                  \
        sp[1] = make_float4(W10, W11, W12, g1);                                  \
        sp[2] = make_float4(W20, W21, W22, g2);                                  \
        sp[3] = make_float4(i10, i11, i21, 0.f);                                 \
    }                                                                            \
    D000=D100; D010=D110; D020=D120; D011=D111; D021=D121; D022=D122;            \
    D100=0; D110=0; D120=0; D111=D211; D121=0; D122=0; D211=0;                   \
    A00=0; A01=0; A02=0; A10=B10; A11=B11; A12=B12; A20=0; A21=0; A22=0;         \
    B10=0; B11=0; B12=0;                                                         \
    r00=r10; r01=r11; r02=r12;                                                   \
    r10=0; r11=r21; r12=0; r21=0;                                                \
} while(0)

__global__ __launch_bounds__(TPB)
void ode_babe_kernel(const float* __restrict__ coeffs,
                     const float* __restrict__ rhs,
                     const float* __restrict__ ivr,
                     const float* __restrict__ steps,
                     float* __restrict__ out)
{
    __shared__ float s_co[E_ * 90];   // coeffs in; reused for x out
    __shared__ float s_rr[E_ * 30];
    __shared__ float s_st[E_ * 29];
    __shared__ float s_iv[E_ * 4];
    extern __shared__ float s_sv[];   // factor records (dynamic, float4-packed)

    const int tid = threadIdx.x;
    const size_t blk = (size_t)blockIdx.x * E_;

    // ---- coalesced staging ----
    {
        const float4* g = (const float4*)(coeffs + blk * 90);
        float4* s = (float4*)s_co;
        for (int k = tid; k < E_*90/4; k += TPB) s[k] = g[k];
    }
    {
        const float4* g = (const float4*)(rhs + blk * 30);
        float4* s = (float4*)s_rr;
        for (int k = tid; k < E_*30/4; k += TPB) s[k] = g[k];
    }
    {
        const float4* g = (const float4*)(steps + blk * 29);
        float4* s = (float4*)s_st;
        for (int k = tid; k < E_*29/4; k += TPB) s[k] = g[k];
    }
    {
        const float4* g = (const float4*)(ivr + blk * 4);
        float4* s = (float4*)s_iv;
        for (int k = tid; k < E_*4/4; k += TPB) s[k] = g[k];
    }
    __syncthreads();

    const int  e   = tid >> 1;          // element index within block
    const bool top = (tid & 1) == 0;    // even lane = top, odd = bottom

    const float* cc  = s_co + e * 90;
    const float* rrp = s_rr + e * 30;
    const float* stp = s_st + e * 29;

    // direction constants (uniform code path)
    const float sgn   = top ? 1.f : -1.f;
    const int   cbase = top ? 0 : 87;
    const int   cstep = top ? 3 : -3;
    const int   rbase = top ? 0 : 29;
    const int   rstep = top ? 1 : -1;
    const int   hbase = top ? 0 : 28;
    const int   hstep = top ? 1 : -1;

    const float one_t = top ? 1.f : 0.f;
    const float iva0 = top ? s_iv[e*4+0] : 0.f;
    const float iva1 = top ? s_iv[e*4+1] : 0.f;
    const float iva2 = top ? s_iv[e*4+2] : 0.f;
    const float iva3 = top ? s_iv[e*4+3] : 0.f;

    float D000=0,D010=0,D020=0,D011=0,D021=0,D022=0;
    float D100=0,D110=0,D120=0,D111=0,D121=0,D122=0;
    float D211=0;
    float A00=0,A01=0,A02=0,A10=0,A11=0,A12=0,A20=0,A21=0,A22=0;
    float B10=0,B11=0,B12=0;
    float r00=0,r01=0,r02=0, r10=0,r11=0,r12=0, r21=0;

    #pragma unroll
    for (int s = 0; s < KH_; s++) {
        const float* cb = cc + cbase + cstep*s;
        float c0=cb[0], c1=cb[1], c2=cb[2];
        float rv = rrp[rbase + rstep*s];

        D000 += c0*c0; D010 += c1*c0; D020 += c2*c0;
        D011 += c1*c1; D021 += c2*c1; D022 += c2*c2;
        r00 += c0*rv; r01 += c1*rv; r02 += c2*rv;
        if (s == 0) { D000 += one_t; D011 += one_t; r00 += iva0; r01 += iva1; }
        if (s == 1) { D000 += one_t; D011 += one_t; r00 += iva2; r01 += iva3; }

        float h = sgn * stp[hbase + hstep*s];
        float h2 = h*h, h3 = h2*h, h4 = h2*h2;
        D000 += 2.f;       D010 += h;          D020 += 0.5f*h2;
        D011 += 3.f*h2;    D021 += 1.5f*h3;    D022 += 1.25f*h4;
        A00  += -2.f;      A01  += -h;         A02  += -0.5f*h2;
        A10  += h;         A11  += -2.f*h2;    A12  += -h3;
        A20  += -0.5f*h2;  A21  += h3;
        D100 += 2.f;       D110 += -h;         D120 += 0.5f*h2;
        D111 += 3.f*h2;    D121 += -1.5f*h3;   D122 += 1.25f*h4;

        float cp = h + sgn * stp[hbase + hstep*(s+1)];
        D011 += 1.f;  A21 += cp;
        D122 += cp*cp; B12 += -cp; D211 += 1.f;

        ELIM_STEP(s);
    }

    // ---- interface carry exchange via warp shuffle (partner = lane^1) ----
    float te[14], be[14];
    {
        float mine[14] = { D000, D010, D020, D011, D021, D022, D111,
                           A10, A11, A12, r00, r01, r02, r11 };
        #pragma unroll
        for (int i = 0; i < 14; i++) {
            float theirs = __shfl_xor_sync(0xffffffffu, mine[i], 1);
            te[i] = top ? mine[i] : theirs;
            be[i] = top ? theirs  : mine[i];
        }
    }

    // ---- interface: 6x6 SPD solve for x_14, x_15 (computed by both lanes) ----
    float x10_, x11_, x12_, x20_, x21_, x22_;
    {
        float h = stp[KH_];
        float h2 = h*h, h3 = h2*h, h4 = h2*h2;
        float cK0=cc[3*KH_], cK1=cc[3*KH_+1], cK2=cc[3*KH_+2];
        float cL0=cc[3*KH_+3], cL1=cc[3*KH_+4], cL2=cc[3*KH_+5];
        float rvK = rrp[KH_], rvL = rrp[KH_+1];

        float d00 = te[0] + cK0*cK0 + 2.f;
        float d10 = te[1] + cK1*cK0 + h;
        float d20 = te[2] + cK2*cK0 + 0.5f*h2;
        float d11 = te[3] + cK1*cK1 + 3.f*h2 + be[6];
        float d21 = te[4] + cK2*cK1 + 1.5f*h3;
        float d22 = te[5] + cK2*cK2 + 1.25f*h4;
        float e00 = be[0] + cL0*cL0 + 2.f;
        float e10 = be[1] + cL1*cL0 - h;
        float e20 = be[2] + cL2*cL0 + 0.5f*h2;
        float e11 = be[3] + cL1*cL1 + 3.f*h2 + te[6];
        float e21 = be[4] + cL2*cL1 - 1.5f*h3;
        float e22 = be[5] + cL2*cL2 + 1.25f*h4;
        float a00 = -2.f;
        float a01 = -h        + be[7];
        float a02 = -0.5f*h2;
        float a10 =  h        + te[7];
        float a11 = -2.f*h2   + te[8] + be[8];
        float a12 = -h3       + te[9];
        float a20 = -0.5f*h2;
        float a21 =  h3       + be[9];
        float a22 = 0.f;
        float rk0 = te[10] + cK0*rvK;
        float rk1 = te[11] + cK1*rvK + be[13];
        float rk2 = te[12] + cK2*rvK;
        float rl0 = be[10] + cL0*rvL;
        float rl1 = be[11] + cL1*rvL + te[13];
        float rl2 = be[12] + cL2*rvL;

        float il00 = rsqrtf(d00);
        float l10 = d10*il00, l20 = d20*il00;
        float il11 = rsqrtf(d11 - l10*l10);
        float l21 = (d21 - l20*l10)*il11;
        float il22 = rsqrtf(d22 - l20*l20 - l21*l21);
        float w00 = a00*il00, w01 = (a01 - w00*l10)*il11, w02 = (a02 - w00*l20 - w01*l21)*il22;
        float w10 = a10*il00, w11 = (a11 - w10*l10)*il11, w12 = (a12 - w10*l20 - w11*l21)*il22;
        float w20 = a20*il00, w21 = (a21 - w20*l10)*il11, w22 = (a22 - w20*l20 - w21*l21)*il22;
        float s00 = e00 - (w00*w00 + w01*w01 + w02*w02);
        float s10 = e10 - (w10*w00 + w11*w01 + w12*w02);
        float s20 = e20 - (w20*w00 + w21*w01 + w22*w02);
        float s11 = e11 - (w10*w10 + w11*w11 + w12*w12);
        float s21 = e21 - (w20*w10 + w21*w11 + w22*w12);
        float s22 = e22 - (w20*w20 + w21*w21 + w22*w22);
        float jl00 = rsqrtf(s00);
        float k10 = s10*jl00, k20 = s20*jl00;
        float jl11 = rsqrtf(s11 - k10*k10);
        float k21 = (s21 - k20*k10)*jl11;
        float jl22 = rsqrtf(s22 - k20*k20 - k21*k21);
        float y10 = rk0*il00;
        float y11 = (rk1 - y10*l10)*il11;
        float y12 = (rk2 - y10*l20 - y11*l21)*il22;
        float t0 = rl0 - (w00*y10 + w01*y11 + w02*y12);
        float t1 = rl1 - (w10*y10 + w11*y11 + w12*y12);
        float t2 = rl2 - (w20*y10 + w21*y11 + w22*y12);
        float y20 = t0*jl00;
        float y21 = (t1 - y20*k10)*jl11;
        float y22 = (t2 - y20*k20 - y21*k21)*jl22;
        x22_ = y22*jl22;
        x21_ = (y21 - k21*x22_)*jl11;
        x20_ = (y20 - k10*x21_ - k20*x22_)*jl00;
        float z0 = y10 - (w00*x20_ + w10*x21_ + w20*x22_);
        float z1 = y11 - (w01*x20_ + w11*x21_ + w21*x22_);
        float z2 = y12 - (w02*x20_ + w12*x21_ + w22*x22_);
        x12_ = z2*il22;
        x11_ = (z1 - l21*x12_)*il11;
        x10_ = (z0 - l10*x11_ - l20*x12_)*il00;
    }

    // ---- back substitution: x = g - W^T x_next + xp1*icol1 ----
    float* ox = s_co + e * 90;   // coeffs consumed; reuse as output staging
    if (top) {
        ox[3*KH_+0]=x10_; ox[3*KH_+1]=x11_; ox[3*KH_+2]=x12_;
        ox[3*KH_+3]=x20_; ox[3*KH_+4]=x21_; ox[3*KH_+5]=x22_;
    }
    float xn0 = top ? x10_ : x20_;
    float xn1 = top ? x11_ : x21_;
    float xn2 = top ? x12_ : x22_;
    float xp1 = top ? x21_ : x11_;
    const int obase = top ? 0 : 87;
    const int ostep = top ? 3 : -3;

    const float4* sb = (const float4*)s_sv;
    float4 p0, p1, p2, p3;
    {
        const float4* sp = sb + ((KH_-1)*TPB + tid)*SV_V;
        p0 = sp[0]; p1 = sp[1]; p2 = sp[2]; p3 = sp[3];
    }

    #pragma unroll
    for (int k = KH_-1; k >= 0; k--) {
        float4 q0 = p0, q1 = p1, q2 = p2, q3 = p3;
        if (k > 0) {   // prefetch next record off the chain
            const float4* sp = sb + ((k-1)*TPB + tid)*SV_V;
            p0 = sp[0]; p1 = sp[1]; p2 = sp[2]; p3 = sp[3];
        }
        // fields: q0=(W00,W01,W02,g0) q1=(W10,W11,W12,g1)
        //         q2=(W20,W21,W22,g2) q3=(i10,i11,i21,-)
        float x0 = q0.w - (q0.x*xn0 + q1.x*xn1 + q2.x*xn2) + xp1*q3.x;
        float x1 = q1.w - (q0.y*xn0 + q1.y*xn1 + q2.y*xn2) + xp1*q3.y;
        float x2 = q2.w - (q0.z*xn0 + q1.z*xn1 + q2.z*xn2) + xp1*q3.z;
        float* op = ox + obase + ostep*k;
        op[0] = x0; op[1] = x1; op[2] = x2;
        xp1 = xn1; xn0 = x0; xn1 = x1; xn2 = x2;
    }

    // ---- coalesced store-out ----
    __syncthreads();
    {
        const float4* s = (const float4*)s_co;
        float4* g = (float4*)(out + blk * 90);
        for (int k = tid; k < E_*90/4; k += TPB) g[k] = s[k];
    }
}

extern "C" void kernel_launch(void* const* d_in, const int* in_sizes, int n_in,
                              void* d_out, int out_size) {
    const float* coeffs = (const float*)d_in[0];
    const float* rhs    = (const float*)d_in[1];
    const float* iv_rhs = (const float*)d_in[2];
    const float* steps  = (const float*)d_in[3];
    float* out = (float*)d_out;

    cudaFuncSetAttribute(ode_babe_kernel,
                         cudaFuncAttributeMaxDynamicSharedMemorySize, SV_BYTES);

    dim3 block(TPB);
    dim3 grid(BS_ / E_);   // 256 blocks
    ode_babe_kernel<<<grid, block, SV_BYTES>>>(coeffs, rhs, iv_rhs, steps, out);
}

// round 15
// speedup vs baseline: 1.0821x; 1.0773x over previous
#include <cuda_runtime.h>

#define BS_  8192
#define NS_  30
#define KH_  14      // each side eliminates 14 blocks; interface blocks 14,15
#define E_   32      // elements per block
#define TPB  64      // lane 2k = top half of elem k, lane 2k+1 = bottom half

#define SV_V 5       // record stride: 5 float4 (80B) keeps 8-lane LDS.128 conflict-free
#define SV_BYTES (SV_V * 16 * KH_ * TPB)   // 71680 B dynamic smem

// Streaming block elimination via adjugate inverse (1 RCP, parallel FMA trees).
// Record stored: W = A*invD (9), g = invD*r0 (3), invD col1 (3).
#define ELIM_STEP(SVIDX) do {                                                    \
    float adj00 = D011*D022 - D021*D021;                                         \
    float adj10 = D020*D021 - D010*D022;                                         \
    float adj20 = D010*D021 - D011*D020;                                         \
    float adj11 = D000*D022 - D020*D020;                                         \
    float adj21 = D010*D020 - D000*D021;                                         \
    float adj22 = D000*D011 - D010*D010;                                         \
    float det = D000*adj00 + D010*adj10 + D020*adj20;                            \
    float idet; asm("rcp.approx.f32 %0, %1;" : "=f"(idet) : "f"(det));           \
    float i00=adj00*idet, i10=adj10*idet, i20=adj20*idet;                        \
    float i11=adj11*idet, i21=adj21*idet, i22=adj22*idet;                        \
    float g0 = i00*r00 + i10*r01 + i20*r02;                                      \
    float g1 = i10*r00 + i11*r01 + i21*r02;                                      \
    float g2 = i20*r00 + i21*r01 + i22*r02;                                      \
    float W00 = A00*i00 + A01*i10 + A02*i20;                                     \
    float W01 = A00*i10 + A01*i11 + A02*i21;                                     \
    float W02 = A00*i20 + A01*i21 + A02*i22;                                     \
    float W10 = A10*i00 + A11*i10 + A12*i20;                                     \
    float W11 = A10*i10 + A11*i11 + A12*i21;                                     \
    float W12 = A10*i20 + A11*i21 + A12*i22;                                     \
    float W20 = A20*i00 + A21*i10 + A22*i20;                                     \
    float W21 = A20*i10 + A21*i11 + A22*i21;                                     \
    float W22 = A20*i20 + A21*i21 + A22*i22;                                     \
    r10 -= A00*g0 + A01*g1 + A02*g2;                                             \
    r11 -= A10*g0 + A11*g1 + A12*g2;                                             \
    r12 -= A20*g0 + A21*g1 + A22*g2;                                             \
    r21 += g1;                                                                   \
    D100 -= W00*A00 + W01*A01 + W02*A02;                                         \
    D110 -= W10*A00 + W11*A01 + W12*A02;                                         \
    D120 -= W20*A00 + W21*A01 + W22*A02;                                         \
    D111 -= W10*A10 + W11*A11 + W12*A12;                                         \
    D121 -= W20*A10 + W21*A11 + W22*A12;                                         \
    D122 -= W20*A20 + W21*A21 + W22*A22;                                         \
    B10 += i10*A00 + i11*A01 + i21*A02;                                          \
    B11 += i10*A10 + i11*A11 + i21*A12;                                          \
    B12 += i10*A20 + i11*A21 + i21*A22;                                          \
    D211 -= i11;                                                                 \
    {                                                                            \
        float4* sp = ((float4*)s_sv) + ((SVIDX)*TPB + tid)*SV_V;                 \
        sp[0] = make_float4(W00, W01, W02, g0);                                  \
        sp[1] = make_float4(W10, W11, W12, g1);                                  \
        sp[2] = make_float4(W20, W21, W22, g2);                                  \
        sp[3] = make_float4(i10, i11, i21, 0.f);                                 \
    }                                                                            \
    D000=D100; D010=D110; D020=D120; D011=D111; D021=D121; D022=D122;            \
    D100=0; D110=0; D120=0; D111=D211; D121=0; D122=0; D211=0;                   \
    A00=0; A01=0; A02=0; A10=B10; A11=B11; A12=B12; A20=0; A21=0; A22=0;         \
    B10=0; B11=0; B12=0;                                                         \
    r00=r10; r01=r11; r02=r12;                                                   \
    r10=0; r11=r21; r12=0; r21=0;                                                \
} while(0)

__global__ __launch_bounds__(TPB)
void ode_babe_kernel(const float* __restrict__ coeffs,
                     const float* __restrict__ rhs,
                     const float* __restrict__ ivr,
                     const float* __restrict__ steps,
                     float* __restrict__ out)
{
    __shared__ float s_co[E_ * 90];   // coeffs in; reused for x out
    __shared__ float s_rr[E_ * 30];
    __shared__ float s_st[E_ * 29];
    __shared__ float s_iv[E_ * 4];
    extern __shared__ float s_sv[];   // factor records (dynamic, float4-packed)

    const int tid = threadIdx.x;
    const size_t blk = (size_t)blockIdx.x * E_;

    // ---- coalesced staging ----
    {
        const float4* g = (const float4*)(coeffs + blk * 90);
        float4* s = (float4*)s_co;
        for (int k = tid; k < E_*90/4; k += TPB) s[k] = g[k];
    }
    {
        const float4* g = (const float4*)(rhs + blk * 30);
        float4* s = (float4*)s_rr;
        for (int k = tid; k < E_*30/4; k += TPB) s[k] = g[k];
    }
    {
        const float4* g = (const float4*)(steps + blk * 29);
        float4* s = (float4*)s_st;
        for (int k = tid; k < E_*29/4; k += TPB) s[k] = g[k];
    }
    {
        const float4* g = (const float4*)(ivr + blk * 4);
        float4* s = (float4*)s_iv;
        for (int k = tid; k < E_*4/4; k += TPB) s[k] = g[k];
    }
    __syncthreads();

    const int  e   = tid >> 1;          // element index within block
    const bool top = (tid & 1) == 0;    // even lane = top, odd = bottom

    const float* cc  = s_co + e * 90;
    const float* rrp = s_rr + e * 30;
    const float* stp = s_st + e * 29;

    // direction constants (uniform code path)
    const float sgn   = top ? 1.f : -1.f;
    const int   cbase = top ? 0 : 87;
    const int   cstep = top ? 3 : -3;
    const int   rbase = top ? 0 : 29;
    const int   rstep = top ? 1 : -1;
    const int   hbase = top ? 0 : 28;
    const int   hstep = top ? 1 : -1;

    const float one_t = top ? 1.f : 0.f;
    const float iva0 = top ? s_iv[e*4+0] : 0.f;
    const float iva1 = top ? s_iv[e*4+1] : 0.f;
    const float iva2 = top ? s_iv[e*4+2] : 0.f;
    const float iva3 = top ? s_iv[e*4+3] : 0.f;

    float D000=0,D010=0,D020=0,D011=0,D021=0,D022=0;
    float D100=0,D110=0,D120=0,D111=0,D121=0,D122=0;
    float D211=0;
    float A00=0,A01=0,A02=0,A10=0,A11=0,A12=0,A20=0,A21=0,A22=0;
    float B10=0,B11=0,B12=0;
    float r00=0,r01=0,r02=0, r10=0,r11=0,r12=0, r21=0;

    // ---- software-prefetched per-step operands (LDS off the chain) ----
    float pc0 = cc[cbase], pc1 = cc[cbase+1], pc2 = cc[cbase+2];
    float prv = rrp[rbase];
    float h   = sgn * stp[hbase];
    float hn  = sgn * stp[hbase + hstep];

    #pragma unroll
    for (int s = 0; s < KH_; s++) {
        float c0=pc0, c1=pc1, c2=pc2, rv=prv;
        float cp = h + hn;

        // issue next iteration's smem loads NOW (consumed next step)
        {
            const float* cbn = cc + cbase + cstep*(s+1);
            pc0 = cbn[0]; pc1 = cbn[1]; pc2 = cbn[2];
            prv = rrp[rbase + rstep*(s+1)];
        }
        float hn2 = sgn * stp[hbase + hstep*(s+2 <= KH_+1 ? s+2 : KH_+1)];

        D000 += c0*c0; D010 += c1*c0; D020 += c2*c0;
        D011 += c1*c1; D021 += c2*c1; D022 += c2*c2;
        r00 += c0*rv; r01 += c1*rv; r02 += c2*rv;
        if (s == 0) { D000 += one_t; D011 += one_t; r00 += iva0; r01 += iva1; }
        if (s == 1) { D000 += one_t; D011 += one_t; r00 += iva2; r01 += iva3; }

        float h2 = h*h, h3 = h2*h, h4 = h2*h2;
        D000 += 2.f;       D010 += h;          D020 += 0.5f*h2;
        D011 += 3.f*h2;    D021 += 1.5f*h3;    D022 += 1.25f*h4;
        A00  += -2.f;      A01  += -h;         A02  += -0.5f*h2;
        A10  += h;         A11  += -2.f*h2;    A12  += -h3;
        A20  += -0.5f*h2;  A21  += h3;
        D100 += 2.f;       D110 += -h;         D120 += 0.5f*h2;
        D111 += 3.f*h2;    D121 += -1.5f*h3;   D122 += 1.25f*h4;

        D011 += 1.f;  A21 += cp;
        D122 += cp*cp; B12 += -cp; D211 += 1.f;

        ELIM_STEP(s);

        h = hn; hn = hn2;
    }

    // ---- interface carry exchange via warp shuffle (partner = lane^1) ----
    float te[14], be[14];
    {
        float mine[14] = { D000, D010, D020, D011, D021, D022, D111,
                           A10, A11, A12, r00, r01, r02, r11 };
        #pragma unroll
        for (int i = 0; i < 14; i++) {
            float theirs = __shfl_xor_sync(0xffffffffu, mine[i], 1);
            te[i] = top ? mine[i] : theirs;
            be[i] = top ? theirs  : mine[i];
        }
    }

    // ---- interface: 6x6 SPD solve via two 3x3 adjugate inverses ----
    float x10_, x11_, x12_, x20_, x21_, x22_;
    {
        float h = stp[KH_];
        float h2 = h*h, h3 = h2*h, h4 = h2*h2;
        float cK0=cc[3*KH_], cK1=cc[3*KH_+1], cK2=cc[3*KH_+2];
        float cL0=cc[3*KH_+3], cL1=cc[3*KH_+4], cL2=cc[3*KH_+5];
        float rvK = rrp[KH_], rvL = rrp[KH_+1];

        float d00 = te[0] + cK0*cK0 + 2.f;
        float d10 = te[1] + cK1*cK0 + h;
        float d20 = te[2] + cK2*cK0 + 0.5f*h2;
        float d11 = te[3] + cK1*cK1 + 3.f*h2 + be[6];
        float d21 = te[4] + cK2*cK1 + 1.5f*h3;
        float d22 = te[5] + cK2*cK2 + 1.25f*h4;
        float e00 = be[0] + cL0*cL0 + 2.f;
        float e10 = be[1] + cL1*cL0 - h;
        float e20 = be[2] + cL2*cL0 + 0.5f*h2;
        float e11 = be[3] + cL1*cL1 + 3.f*h2 + te[6];
        float e21 = be[4] + cL2*cL1 - 1.5f*h3;
        float e22 = be[5] + cL2*cL2 + 1.25f*h4;
        float a00 = -2.f;
        float a01 = -h        + be[7];
        float a02 = -0.5f*h2;
        float a10 =  h        + te[7];
        float a11 = -2.f*h2   + te[8] + be[8];
        float a12 = -h3       + te[9];
        float a20 = -0.5f*h2;
        float a21 =  h3       + be[9];
        float a22 = 0.f;
        float rk0 = te[10] + cK0*rvK;
        float rk1 = te[11] + cK1*rvK + be[13];
        float rk2 = te[12] + cK2*rvK;
        float rl0 = be[10] + cL0*rvL;
        float rl1 = be[11] + cL1*rvL + te[13];
        float rl2 = be[12] + cL2*rvL;

        // invD14 via adjugate
        float adj00 = d11*d22 - d21*d21;
        float adj10 = d20*d21 - d10*d22;
        float adj20 = d10*d21 - d11*d20;
        float adj11 = d00*d22 - d20*d20;
        float adj21 = d10*d20 - d00*d21;
        float adj22 = d00*d11 - d10*d10;
        float det = d00*adj00 + d10*adj10 + d20*adj20;
        float idet; asm("rcp.approx.f32 %0, %1;" : "=f"(idet) : "f"(det));
        float i00=adj00*idet, i10=adj10*idet, i20=adj20*idet;
        float i11=adj11*idet, i21=adj21*idet, i22=adj22*idet;

        // g14 = invD14 * rk ; W = a * invD14
        float g0 = i00*rk0 + i10*rk1 + i20*rk2;
        float g1 = i10*rk0 + i11*rk1 + i21*rk2;
        float g2 = i20*rk0 + i21*rk1 + i22*rk2;
        float W00 = a00*i00 + a01*i10 + a02*i20;
        float W01 = a00*i10 + a01*i11 + a02*i21;
        float W02 = a00*i20 + a01*i21 + a02*i22;
        float W10 = a10*i00 + a11*i10 + a12*i20;
        float W11 = a10*i10 + a11*i11 + a12*i21;
        float W12 = a10*i20 + a11*i21 + a12*i22;
        float W20 = a20*i00 + a21*i10 + a22*i20;
        float W21 = a20*i10 + a21*i11 + a22*i21;
        float W22 = a20*i20 + a21*i21 + a22*i22;

        // S = D15 - W a^T  (symmetric)
        float s00 = e00 - (W00*a00 + W01*a01 + W02*a02);
        float s10 = e10 - (W10*a00 + W11*a01 + W12*a02);
        float s20 = e20 - (W20*a00 + W21*a01 + W22*a02);
        float s11 = e11 - (W10*a10 + W11*a11 + W12*a12);
        float s21 = e21 - (W20*a10 + W21*a11 + W22*a12);
        float s22 = e22 - (W20*a20 + W21*a21 + W22*a22);

        // t = rl - W rk
        float t0 = rl0 - (W00*rk0 + W01*rk1 + W02*rk2);
        float t1 = rl1 - (W10*rk0 + W11*rk1 + W12*rk2);
        float t2 = rl2 - (W20*rk0 + W21*rk1 + W22*rk2);

        // invS via adjugate; x15 = invS t
        float sj00 = s11*s22 - s21*s21;
        float sj10 = s20*s21 - s10*s22;
        float sj20 = s10*s21 - s11*s20;
        float sj11 = s00*s22 - s20*s20;
        float sj21 = s10*s20 - s00*s21;
        float sj22 = s00*s11 - s10*s10;
        float sdet = s00*sj00 + s10*sj10 + s20*sj20;
        float isdet; asm("rcp.approx.f32 %0, %1;" : "=f"(isdet) : "f"(sdet));
        float j00=sj00*isdet, j10=sj10*isdet, j20=sj20*isdet;
        float j11=sj11*isdet, j21=sj21*isdet, j22=sj22*isdet;
        x20_ = j00*t0 + j10*t1 + j20*t2;
        x21_ = j10*t0 + j11*t1 + j21*t2;
        x22_ = j20*t0 + j21*t1 + j22*t2;

        // x14 = g14 - W^T x15
        x10_ = g0 - (W00*x20_ + W10*x21_ + W20*x22_);
        x11_ = g1 - (W01*x20_ + W11*x21_ + W21*x22_);
        x12_ = g2 - (W02*x20_ + W12*x21_ + W22*x22_);
    }

    // ---- back substitution: x = g - W^T x_next + xp1*icol1 ----
    float* ox = s_co + e * 90;   // coeffs consumed; reuse as output staging
    if (top) {
        ox[3*KH_+0]=x10_; ox[3*KH_+1]=x11_; ox[3*KH_+2]=x12_;
        ox[3*KH_+3]=x20_; ox[3*KH_+4]=x21_; ox[3*KH_+5]=x22_;
    }
    float xn0 = top ? x10_ : x20_;
    float xn1 = top ? x11_ : x21_;
    float xn2 = top ? x12_ : x22_;
    float xp1 = top ? x21_ : x11_;
    const int obase = top ? 0 : 87;
    const int ostep = top ? 3 : -3;

    const float4* sb = (const float4*)s_sv;
    float4 p0, p1, p2, p3;
    {
        const float4* sp = sb + ((KH_-1)*TPB + tid)*SV_V;
        p0 = sp[0]; p1 = sp[1]; p2 = sp[2]; p3 = sp[3];
    }

    #pragma unroll
    for (int k = KH_-1; k >= 0; k--) {
        float4 q0 = p0, q1 = p1, q2 = p2, q3 = p3;
        if (k > 0) {   // prefetch next record off the chain
            const float4* sp = sb + ((k-1)*TPB + tid)*SV_V;
            p0 = sp[0]; p1 = sp[1]; p2 = sp[2]; p3 = sp[3];
        }
        float x0 = q0.w - (q0.x*xn0 + q1.x*xn1 + q2.x*xn2) + xp1*q3.x;
        float x1 = q1.w - (q0.y*xn0 + q1.y*xn1 + q2.y*xn2) + xp1*q3.y;
        float x2 = q2.w - (q0.z*xn0 + q1.z*xn1 + q2.z*xn2) + xp1*q3.z;
        float* op = ox + obase + ostep*k;
        op[0] = x0; op[1] = x1; op[2] = x2;
        xp1 = xn1; xn0 = x0; xn1 = x1; xn2 = x2;
    }

    // ---- coalesced store-out ----
    __syncthreads();
    {
        const float4* s = (const float4*)s_co;
        float4* g = (float4*)(out + blk * 90);
        for (int k = tid; k < E_*90/4; k += TPB) g[k] = s[k];
    }
}

extern "C" void kernel_launch(void* const* d_in, const int* in_sizes, int n_in,
                              void* d_out, int out_size) {
    const float* coeffs = (const float*)d_in[0];
    const float* rhs    = (const float*)d_in[1];
    const float* iv_rhs = (const float*)d_in[2];
    const float* steps  = (const float*)d_in[3];
    float* out = (float*)d_out;

    cudaFuncSetAttribute(ode_babe_kernel,
                         cudaFuncAttributeMaxDynamicSharedMemorySize, SV_BYTES);

    dim3 block(TPB);
    dim3 grid(BS_ / E_);   // 256 blocks
    ode_babe_kernel<<<grid, block, SV_BYTES>>>(coeffs, rhs, iv_rhs, steps, out);
}